// round 5
// baseline (speedup 1.0000x reference)
#include <cuda_runtime.h>

// Fixed problem shapes
#define NBATCH 8
#define NP 64
#define NV 32
#define ND 1626
#define NPAIR 813                    // dir pairs per tile
#define NTILE (NBATCH * NP)          // 512
#define NTHREADS 128
#define NBLK_MAIN ((NTILE * NPAIR) / NTHREADS)   // 3252 exactly

typedef unsigned long long ull;

__device__ float4 g_dirs4[ND];
// Per-tile scratch: 192 floats = {x dup 64, y dup 64, z dup 64}
__device__ __align__(16) float g_scr[NTILE][192];
// Per-tile constants: [0]={mx,my,mz,pm1} [1]={c0,invp,q,qLR}
__device__ __align__(16) float4 g_cst[NTILE][2];

__device__ __forceinline__ float fast_lg2(float x) {
    float r; asm("lg2.approx.ftz.f32 %0, %1;" : "=f"(r) : "f"(x)); return r;
}
__device__ __forceinline__ float fast_ex2(float x) {
    float r; asm("ex2.approx.ftz.f32 %0, %1;" : "=f"(r) : "f"(x)); return r;
}
__device__ __forceinline__ ull pack2(float lo, float hi) {
    ull r; asm("mov.b64 %0, {%1, %2};" : "=l"(r) : "f"(lo), "f"(hi)); return r;
}
__device__ __forceinline__ void unpack2(ull v, float& lo, float& hi) {
    asm("mov.b64 {%0, %1}, %2;" : "=f"(lo), "=f"(hi) : "l"(v));
}
__device__ __forceinline__ ull fma2(ull a, ull b, ull c) {
    ull d; asm("fma.rn.f32x2 %0, %1, %2, %3;" : "=l"(d) : "l"(a), "l"(b), "l"(c)); return d;
}
__device__ __forceinline__ ull mul2(ull a, ull b) {
    ull d; asm("mul.rn.f32x2 %0, %1, %2;" : "=l"(d) : "l"(a), "l"(b)); return d;
}

// Setup kernel: blocks 0..15 build dirs (fp64, matches numpy->fp32 cast);
// blocks 16..143 do per-tile prep, one warp per tile.
__global__ void setup_kernel(const float* __restrict__ vertices,
                             const float* __restrict__ smoothness,
                             float* __restrict__ out)
{
    const int tid = threadIdx.x;
    if (blockIdx.x < 16) {
        __shared__ double c1[30], s1[30], c2[59], s2[59];
        const double PI = 3.141592653589793;
        if (tid < 30) {
            double th = (tid == 0)  ? -PI * 0.5
                      : (tid == 29) ?  PI * 0.5
                      : (double)tid * (PI / 29.0) + (-PI * 0.5);
            c1[tid] = cos(th); s1[tid] = sin(th);
        } else if (tid < 89) {
            int i = tid - 30;
            double th = (i == 0) ? -PI : (double)i * (2.0 * PI / 58.0) + (-PI);
            c2[i] = cos(th); s2[i] = sin(th);
        }
        __syncthreads();
        if (tid < 102) {
            int d = blockIdx.x * 102 + tid;
            if (d < ND) {
                double dx, dy, dz;
                if (d < 1624) {
                    int i1 = d / 58 + 1, i2 = d % 58;
                    dx = c1[i1] * c2[i2]; dy = c1[i1] * s2[i2]; dz = s1[i1];
                } else if (d == 1624) {
                    dx = c1[0] * c2[0];   dy = c1[0] * s2[0];   dz = s1[0];
                } else {
                    dx = c1[29] * c2[0];  dy = c1[29] * s2[0];  dz = s1[29];
                }
                g_dirs4[d] = make_float4((float)dx, (float)dy, (float)dz, 0.0f);
            }
        }
        return;
    }

    // Per-tile prep: warp per tile
    const int bp   = (blockIdx.x - 16) * 4 + (tid >> 5);
    const int lane = tid & 31;

    const float* vin = vertices + (size_t)bp * (NV * 3);
    float x = vin[lane * 3 + 0];
    float y = vin[lane * 3 + 1];
    float z = vin[lane * 3 + 2];

    float sx = x, sy = y, sz = z;
    #pragma unroll
    for (int o = 16; o > 0; o >>= 1) {
        sx += __shfl_xor_sync(0xFFFFFFFFu, sx, o);
        sy += __shfl_xor_sync(0xFFFFFFFFu, sy, o);
        sz += __shfl_xor_sync(0xFFFFFFFFu, sz, o);
    }
    const float mx = sx * (1.0f / 32.0f);
    const float my = sy * (1.0f / 32.0f);
    const float mz = sz * (1.0f / 32.0f);

    const float lvx = x - mx, lvy = y - my, lvz = z - mz;
    float r2 = lvx * lvx + lvy * lvy + lvz * lvz;
    #pragma unroll
    for (int o = 16; o > 0; o >>= 1)
        r2 = fmaxf(r2, __shfl_xor_sync(0xFFFFFFFFu, r2, o));

    float* scr = g_scr[bp];
    scr[2 * lane + 0]       = lvx;  scr[2 * lane + 1]       = lvx;
    scr[64 + 2 * lane + 0]  = lvy;  scr[64 + 2 * lane + 1]  = lvy;
    scr[128 + 2 * lane + 0] = lvz;  scr[128 + 2 * lane + 1] = lvz;

    // Output sections (tuple flattened in reference order)
    float* const out_ov   = out + (size_t)NBATCH * NP * ND * 7;
    float* const out_re   = out_ov + NTILE;
    float* const out_mean = out_re + NTILE;
    float* const out_lv   = out_mean + NTILE * 3;

    float* olv = out_lv + (size_t)bp * (NV * 3) + lane * 3;
    olv[0] = lvx; olv[1] = lvy; olv[2] = lvz;

    if (lane == 0) {
        const float p    = smoothness[bp];
        const float pm1  = p - 1.0f;
        const float invp = 1.0f / p;
        const float q    = pm1 * invp;
        const float LR   = 0.5f * fast_lg2(r2);   // lg2(max ||lv||)
        g_cst[bp][0] = make_float4(mx, my, mz, pm1);
        g_cst[bp][1] = make_float4(-pm1 * LR, invp, q, q * LR);
        out_ov[bp] = 0.0f;
        out_re[bp] = 0.0f;
        out_mean[bp * 3 + 0] = mx;
        out_mean[bp * 3 + 1] = my;
        out_mean[bp * 3 + 2] = mz;
    }
}

__global__ __launch_bounds__(NTHREADS, 7) void spt_kernel(float* __restrict__ out)
{
    const int f  = blockIdx.x * NTHREADS + threadIdx.x;   // pair index 0..416255
    const int bp = f / NPAIR;
    const int d0 = (f - bp * NPAIR) * 2;                  // even; pair {d0, d0+1}

    const float4 DA = g_dirs4[d0];
    const float4 DB = g_dirs4[d0 + 1];
    const ull dx2 = pack2(DA.x, DB.x);
    const ull dy2 = pack2(DA.y, DB.y);
    const ull dz2 = pack2(DA.z, DB.z);

    const float4 cm = g_cst[bp][0];   // mx,my,mz,pm1
    const float4 cp = g_cst[bp][1];   // c0,invp,q,qLR
    const ull pm12 = pack2(cm.w, cm.w);
    const ull c02  = pack2(cp.x, cp.x);

    const ulonglong2* __restrict__ px =
        reinterpret_cast<const ulonglong2*>(g_scr[bp]);        // 16 entries x
    const ulonglong2* __restrict__ py = px + 16;               // y
    const ulonglong2* __restrict__ pz = px + 32;               // z

    ull ax2 = 0, ay2 = 0, az2 = 0;   // 0.0f bit patterns

    #pragma unroll
    for (int j = 0; j < 16; j++) {
        ulonglong2 X = px[j], Y = py[j], Z = pz[j];
        #define VSTEP(XX, YY, ZZ)                                       \
        {                                                               \
            ull z2 = fma2(dz2, ZZ, fma2(dy2, YY, mul2(dx2, XX)));       \
            float zA, zB; unpack2(z2, zA, zB);                          \
            zA = fmaxf(zA, 0.0f); zB = fmaxf(zB, 0.0f);                 \
            ull t2 = fma2(pm12, pack2(fast_lg2(zA), fast_lg2(zB)), c02);\
            float tA, tB; unpack2(t2, tA, tB);                          \
            ull e2 = pack2(fast_ex2(tA), fast_ex2(tB));                 \
            ax2 = fma2(e2, XX, ax2);                                    \
            ay2 = fma2(e2, YY, ay2);                                    \
            az2 = fma2(e2, ZZ, az2);                                    \
        }
        VSTEP(X.x, Y.x, Z.x)
        VSTEP(X.y, Y.y, Z.y)
        #undef VSTEP
    }

    float axA, axB, ayA, ayB, azA, azB;
    unpack2(ax2, axA, axB); unpack2(ay2, ayA, ayB); unpack2(az2, azA, azB);

    // S = d . a   (exact reassociation of sum(e*z))
    const float SA = fmaf(DA.z, azA, fmaf(DA.y, ayA, DA.x * axA));
    const float SB = fmaf(DB.z, azB, fmaf(DB.y, ayB, DB.x * axB));

    const float invp = cp.y, q = cp.z, qLR = cp.w;
    const float LSA = fast_lg2(fmaxf(SA, 1e-35f));
    const float LSB = fast_lg2(fmaxf(SB, 1e-35f));
    const float houtA  = fast_ex2(fmaf(invp, LSA, qLR));
    const float houtB  = fast_ex2(fmaf(invp, LSB, qLR));
    const float scaleA = fast_ex2(fmaf(-q, LSA, qLR));
    const float scaleB = fast_ex2(fmaf(-q, LSB, qLR));

    const float pAx = fmaf(axA, scaleA, cm.x);
    const float pAy = fmaf(ayA, scaleA, cm.y);
    const float pAz = fmaf(azA, scaleA, cm.z);
    const float pBx = fmaf(axB, scaleB, cm.x);
    const float pBy = fmaf(ayB, scaleB, cm.y);
    const float pBz = fmaf(azB, scaleB, cm.z);

    float* const out_points = out;
    float* const out_dh     = out + (size_t)NBATCH * NP * ND * 3;

    const size_t bd = (size_t)bp * ND + d0;
    float2* p2 = reinterpret_cast<float2*>(out_points + bd * 3);
    p2[0] = make_float2(pAx, pAy);
    p2[1] = make_float2(pAz, pBx);
    p2[2] = make_float2(pBy, pBz);

    float4* dh4 = reinterpret_cast<float4*>(out_dh) + bd;
    dh4[0] = make_float4(DA.x, DA.y, DA.z, houtA);
    dh4[1] = make_float4(DB.x, DB.y, DB.z, houtB);
}

extern "C" void kernel_launch(void* const* d_in, const int* in_sizes, int n_in,
                              void* d_out, int out_size) {
    const float* vertices   = (const float*)d_in[0];   // (8,64,32,3)
    const float* smoothness = (const float*)d_in[1];   // (8,64)
    float* out = (float*)d_out;

    setup_kernel<<<16 + NTILE / 4, NTHREADS>>>(vertices, smoothness, out);
    spt_kernel<<<NBLK_MAIN, NTHREADS>>>(out);
}

// round 6
// speedup vs baseline: 1.0155x; 1.0155x over previous
#include <cuda_runtime.h>

// Fixed problem shapes
#define NBATCH 8
#define NP 64
#define NV 32
#define ND 1626
#define NPAIR 813                    // dir pairs per tile
#define NTILE (NBATCH * NP)          // 512
#define NTHREADS 128
#define NBLK_MAIN ((NTILE * NPAIR) / NTHREADS)   // 3252 exactly

typedef unsigned long long ull;

__device__ float4 g_dirs4[ND];
// Per-tile scratch: 192 floats = {x dup 64, y dup 64, z dup 64}
__device__ __align__(16) float g_scr[NTILE][192];
// Per-tile constants: [0]={mx,my,mz,pm1} [1]={c0,invp,q,qLR}
__device__ __align__(16) float4 g_cst[NTILE][2];

__device__ __forceinline__ float fast_lg2(float x) {
    float r; asm("lg2.approx.ftz.f32 %0, %1;" : "=f"(r) : "f"(x)); return r;
}
__device__ __forceinline__ float fast_ex2(float x) {
    float r; asm("ex2.approx.ftz.f32 %0, %1;" : "=f"(r) : "f"(x)); return r;
}
__device__ __forceinline__ ull pack2(float lo, float hi) {
    ull r; asm("mov.b64 %0, {%1, %2};" : "=l"(r) : "f"(lo), "f"(hi)); return r;
}
__device__ __forceinline__ void unpack2(ull v, float& lo, float& hi) {
    asm("mov.b64 {%0, %1}, %2;" : "=f"(lo), "=f"(hi) : "l"(v));
}
__device__ __forceinline__ ull fma2(ull a, ull b, ull c) {
    ull d; asm("fma.rn.f32x2 %0, %1, %2, %3;" : "=l"(d) : "l"(a), "l"(b), "l"(c)); return d;
}
__device__ __forceinline__ ull mul2(ull a, ull b) {
    ull d; asm("mul.rn.f32x2 %0, %1, %2;" : "=l"(d) : "l"(a), "l"(b)); return d;
}

// Setup kernel: blocks 0..15 build dirs (fp64, matches numpy->fp32 cast);
// blocks 16..143 do per-tile prep, one warp per tile.
__global__ void setup_kernel(const float* __restrict__ vertices,
                             const float* __restrict__ smoothness,
                             float* __restrict__ out)
{
    const int tid = threadIdx.x;
    if (blockIdx.x < 16) {
        __shared__ double c1[30], s1[30], c2[59], s2[59];
        const double PI = 3.141592653589793;
        if (tid < 30) {
            double th = (tid == 0)  ? -PI * 0.5
                      : (tid == 29) ?  PI * 0.5
                      : (double)tid * (PI / 29.0) + (-PI * 0.5);
            c1[tid] = cos(th); s1[tid] = sin(th);
        } else if (tid < 89) {
            int i = tid - 30;
            double th = (i == 0) ? -PI : (double)i * (2.0 * PI / 58.0) + (-PI);
            c2[i] = cos(th); s2[i] = sin(th);
        }
        __syncthreads();
        if (tid < 102) {
            int d = blockIdx.x * 102 + tid;
            if (d < ND) {
                double dx, dy, dz;
                if (d < 1624) {
                    int i1 = d / 58 + 1, i2 = d % 58;
                    dx = c1[i1] * c2[i2]; dy = c1[i1] * s2[i2]; dz = s1[i1];
                } else if (d == 1624) {
                    dx = c1[0] * c2[0];   dy = c1[0] * s2[0];   dz = s1[0];
                } else {
                    dx = c1[29] * c2[0];  dy = c1[29] * s2[0];  dz = s1[29];
                }
                g_dirs4[d] = make_float4((float)dx, (float)dy, (float)dz, 0.0f);
            }
        }
        return;
    }

    // Per-tile prep: warp per tile
    const int bp   = (blockIdx.x - 16) * 4 + (tid >> 5);
    const int lane = tid & 31;

    const float* vin = vertices + (size_t)bp * (NV * 3);
    float x = vin[lane * 3 + 0];
    float y = vin[lane * 3 + 1];
    float z = vin[lane * 3 + 2];

    float sx = x, sy = y, sz = z;
    #pragma unroll
    for (int o = 16; o > 0; o >>= 1) {
        sx += __shfl_xor_sync(0xFFFFFFFFu, sx, o);
        sy += __shfl_xor_sync(0xFFFFFFFFu, sy, o);
        sz += __shfl_xor_sync(0xFFFFFFFFu, sz, o);
    }
    const float mx = sx * (1.0f / 32.0f);
    const float my = sy * (1.0f / 32.0f);
    const float mz = sz * (1.0f / 32.0f);

    const float lvx = x - mx, lvy = y - my, lvz = z - mz;
    float r2 = lvx * lvx + lvy * lvy + lvz * lvz;
    #pragma unroll
    for (int o = 16; o > 0; o >>= 1)
        r2 = fmaxf(r2, __shfl_xor_sync(0xFFFFFFFFu, r2, o));

    float* scr = g_scr[bp];
    scr[2 * lane + 0]       = lvx;  scr[2 * lane + 1]       = lvx;
    scr[64 + 2 * lane + 0]  = lvy;  scr[64 + 2 * lane + 1]  = lvy;
    scr[128 + 2 * lane + 0] = lvz;  scr[128 + 2 * lane + 1] = lvz;

    // Output sections (tuple flattened in reference order)
    float* const out_ov   = out + (size_t)NBATCH * NP * ND * 7;
    float* const out_re   = out_ov + NTILE;
    float* const out_mean = out_re + NTILE;
    float* const out_lv   = out_mean + NTILE * 3;

    float* olv = out_lv + (size_t)bp * (NV * 3) + lane * 3;
    olv[0] = lvx; olv[1] = lvy; olv[2] = lvz;

    if (lane == 0) {
        const float p    = smoothness[bp];
        const float pm1  = p - 1.0f;
        const float invp = 1.0f / p;
        const float q    = pm1 * invp;
        const float LR   = 0.5f * fast_lg2(r2);   // lg2(max ||lv||)
        g_cst[bp][0] = make_float4(mx, my, mz, pm1);
        g_cst[bp][1] = make_float4(-pm1 * LR, invp, q, q * LR);
        out_ov[bp] = 0.0f;
        out_re[bp] = 0.0f;
        out_mean[bp * 3 + 0] = mx;
        out_mean[bp * 3 + 1] = my;
        out_mean[bp * 3 + 2] = mz;
    }
}

__global__ __launch_bounds__(NTHREADS, 8) void spt_kernel(float* __restrict__ out)
{
    __shared__ __align__(16) float s_scr[2][192];
    __shared__ __align__(16) float4 s_cst[2][2];

    const int tid = threadIdx.x;
    const int f0  = blockIdx.x * NTHREADS;
    const int bp_first = f0 / NPAIR;
    const int bp_last  = (f0 + NTHREADS - 1) / NPAIR;
    const int ntiles   = bp_last - bp_first + 1;          // 1 or 2

    for (int i = tid; i < ntiles * 192; i += NTHREADS) {
        int t = i / 192, r = i - t * 192;
        s_scr[t][r] = g_scr[bp_first + t][r];
    }
    if (tid < 2 * ntiles)
        s_cst[tid >> 1][tid & 1] = g_cst[bp_first + (tid >> 1)][tid & 1];
    __syncthreads();

    const int f  = f0 + tid;                              // pair index
    const int bp = f / NPAIR;
    const int t  = bp - bp_first;
    const int d0 = (f - bp * NPAIR) * 2;                  // pair {d0, d0+1}

    const float4 DA = g_dirs4[d0];
    const float4 DB = g_dirs4[d0 + 1];
    const ull dx2 = pack2(DA.x, DB.x);
    const ull dy2 = pack2(DA.y, DB.y);
    const ull dz2 = pack2(DA.z, DB.z);

    const float pm1 = s_cst[t][0].w;
    const float c0  = s_cst[t][1].x;

    const ulonglong2* __restrict__ px =
        reinterpret_cast<const ulonglong2*>(s_scr[t]);    // 16 entries x
    const ulonglong2* __restrict__ py = px + 16;          // y
    const ulonglong2* __restrict__ pz = px + 32;          // z

    ull ax2 = 0, ay2 = 0, az2 = 0;                        // 0.0f bit patterns

    #pragma unroll
    for (int j = 0; j < 16; j++) {
        ulonglong2 X = px[j], Y = py[j], Z = pz[j];
        #define VSTEP(XX, YY, ZZ)                                    \
        {                                                            \
            ull z2 = fma2(dz2, ZZ, fma2(dy2, YY, mul2(dx2, XX)));    \
            float zA, zB; unpack2(z2, zA, zB);                       \
            zA = fmaxf(zA, 0.0f); zB = fmaxf(zB, 0.0f);              \
            float eA = fast_ex2(fmaf(pm1, fast_lg2(zA), c0));        \
            float eB = fast_ex2(fmaf(pm1, fast_lg2(zB), c0));        \
            ull e2 = pack2(eA, eB);                                  \
            ax2 = fma2(e2, XX, ax2);                                 \
            ay2 = fma2(e2, YY, ay2);                                 \
            az2 = fma2(e2, ZZ, az2);                                 \
        }
        VSTEP(X.x, Y.x, Z.x)
        VSTEP(X.y, Y.y, Z.y)
        #undef VSTEP
    }

    float axA, axB, ayA, ayB, azA, azB;
    unpack2(ax2, axA, axB); unpack2(ay2, ayA, ayB); unpack2(az2, azA, azB);

    // S = d . a   (exact reassociation of sum(e*z))
    const float SA = fmaf(DA.z, azA, fmaf(DA.y, ayA, DA.x * axA));
    const float SB = fmaf(DB.z, azB, fmaf(DB.y, ayB, DB.x * axB));

    const float4 cm = s_cst[t][0];   // mx,my,mz,pm1
    const float4 cp = s_cst[t][1];   // c0,invp,q,qLR
    const float invp = cp.y, q = cp.z, qLR = cp.w;

    const float LSA = fast_lg2(fmaxf(SA, 1e-35f));
    const float LSB = fast_lg2(fmaxf(SB, 1e-35f));
    const float houtA  = fast_ex2(fmaf(invp, LSA, qLR));
    const float houtB  = fast_ex2(fmaf(invp, LSB, qLR));
    const float scaleA = fast_ex2(fmaf(-q, LSA, qLR));
    const float scaleB = fast_ex2(fmaf(-q, LSB, qLR));

    const float pAx = fmaf(axA, scaleA, cm.x);
    const float pAy = fmaf(ayA, scaleA, cm.y);
    const float pAz = fmaf(azA, scaleA, cm.z);
    const float pBx = fmaf(axB, scaleB, cm.x);
    const float pBy = fmaf(ayB, scaleB, cm.y);
    const float pBz = fmaf(azB, scaleB, cm.z);

    float* const out_points = out;
    float* const out_dh     = out + (size_t)NBATCH * NP * ND * 3;

    const size_t bd = (size_t)bp * ND + d0;
    float2* p2 = reinterpret_cast<float2*>(out_points + bd * 3);
    p2[0] = make_float2(pAx, pAy);
    p2[1] = make_float2(pAz, pBx);
    p2[2] = make_float2(pBy, pBz);

    float4* dh4 = reinterpret_cast<float4*>(out_dh) + bd;
    dh4[0] = make_float4(DA.x, DA.y, DA.z, houtA);
    dh4[1] = make_float4(DB.x, DB.y, DB.z, houtB);
}

extern "C" void kernel_launch(void* const* d_in, const int* in_sizes, int n_in,
                              void* d_out, int out_size) {
    const float* vertices   = (const float*)d_in[0];   // (8,64,32,3)
    const float* smoothness = (const float*)d_in[1];   // (8,64)
    float* out = (float*)d_out;

    setup_kernel<<<16 + NTILE / 4, NTHREADS>>>(vertices, smoothness, out);
    spt_kernel<<<NBLK_MAIN, NTHREADS>>>(out);
}